// round 4
// baseline (speedup 1.0000x reference)
#include <cuda_runtime.h>

// Problem constants (from reference): L=131072, D=512, B=512, S=512
#define DQ 512
#define SQ 512

constexpr int WARPS_PER_BLOCK = 8;
constexpr int THREADS = WARPS_PER_BLOCK * 32;
constexpr int S_PER_BLOCK = 64;  // shortlist entries per block

// 0 = shortlist is int64, 1 = shortlist is int32
__device__ int g_idx_is32;

// Detect shortlist element width. Reads the first 131072 int64 words (1 MB),
// safe under both layouts (int32 buffer is exactly 1 MB, int64 is 2 MB).
// True-int64 indices are < 2^17 so every high word is 0; int32 data packs a
// random second index into the high word -> OR over 131072 pairs is nonzero
// with probability 1 - ~2^-17*... (effectively certain).
__global__ void detect_idx_width_kernel(const unsigned long long* __restrict__ sl) {
    __shared__ unsigned long long red[256];
    unsigned long long acc = 0;
    for (int i = threadIdx.x; i < 131072; i += 256)
        acc |= sl[i];
    red[threadIdx.x] = acc;
    __syncthreads();
    for (int off = 128; off > 0; off >>= 1) {
        if (threadIdx.x < off) red[threadIdx.x] |= red[threadIdx.x + off];
        __syncthreads();
    }
    if (threadIdx.x == 0)
        g_idx_is32 = ((red[0] >> 32) != 0ULL) ? 1 : 0;
}

__global__ __launch_bounds__(THREADS)
void combine_uv_kernel(const float* __restrict__ input,    // [B, D]
                       const float* __restrict__ labels,   // [L, D]
                       const float* __restrict__ weight,   // [L, D]
                       const float* __restrict__ alpha,    // [1, D]
                       const float* __restrict__ beta,     // [1, D]
                       const float* __restrict__ bias,     // [L]
                       const void* __restrict__ shortlist, // [B, S] int32 or int64
                       float* __restrict__ out)            // [B, S]
{
    __shared__ float s_xa[DQ];
    __shared__ float s_xb[DQ];

    const int blocks_per_b = SQ / S_PER_BLOCK;   // 8
    const int b  = blockIdx.x / blocks_per_b;
    const int s0 = (blockIdx.x % blocks_per_b) * S_PER_BLOCK;
    const int tid = threadIdx.x;

    const int is32 = g_idx_is32;
    const int*       sl32 = (const int*)shortlist;
    const long long* sl64 = (const long long*)shortlist;

    // Fold sigmoid(alpha)/sigmoid(beta) into this sample's input row once.
    for (int d = tid; d < DQ; d += THREADS) {
        float x  = input[b * DQ + d];
        float sa = 1.0f / (1.0f + __expf(-alpha[d]));
        float sb = 1.0f / (1.0f + __expf(-beta[d]));
        s_xa[d] = x * sa;
        s_xb[d] = x * sb;
    }
    __syncthreads();

    const int warp = tid >> 5;
    const int lane = tid & 31;

    // Cache the scaled input row in registers (float4 per lane, 4 chunks of 128 floats)
    const float4* xa4 = reinterpret_cast<const float4*>(s_xa);
    const float4* xb4 = reinterpret_cast<const float4*>(s_xb);
    float4 a0 = xa4[lane], a1 = xa4[lane + 32], a2 = xa4[lane + 64], a3 = xa4[lane + 96];
    float4 c0 = xb4[lane], c1 = xb4[lane + 32], c2 = xb4[lane + 64], c3 = xb4[lane + 96];

    // Each warp walks its share of the 64 entries; per entry: gather two 2KB rows.
    for (int e = warp; e < S_PER_BLOCK; e += WARPS_PER_BLOCK) {
        const int s = s0 + e;
        const long long flat = (long long)b * SQ + s;
        const long long idx = is32 ? (long long)sl32[flat] : sl64[flat];

        const float4* w = reinterpret_cast<const float4*>(weight + idx * DQ);
        const float4* v = reinterpret_cast<const float4*>(labels + idx * DQ);

        // 8 independent 16B loads per lane -> good MLP before the FMA chain.
        float4 w0 = w[lane], w1 = w[lane + 32], w2 = w[lane + 64], w3 = w[lane + 96];
        float4 v0 = v[lane], v1 = v[lane + 32], v2 = v[lane + 64], v3 = v[lane + 96];

        float acc;
        acc  = w0.x * a0.x + w0.y * a0.y + w0.z * a0.z + w0.w * a0.w;
        acc += w1.x * a1.x + w1.y * a1.y + w1.z * a1.z + w1.w * a1.w;
        acc += w2.x * a2.x + w2.y * a2.y + w2.z * a2.z + w2.w * a2.w;
        acc += w3.x * a3.x + w3.y * a3.y + w3.z * a3.z + w3.w * a3.w;
        acc += v0.x * c0.x + v0.y * c0.y + v0.z * c0.z + v0.w * c0.w;
        acc += v1.x * c1.x + v1.y * c1.y + v1.z * c1.z + v1.w * c1.w;
        acc += v2.x * c2.x + v2.y * c2.y + v2.z * c2.z + v2.w * c2.w;
        acc += v3.x * c3.x + v3.y * c3.y + v3.z * c3.z + v3.w * c3.w;

        // Warp tree reduction
        #pragma unroll
        for (int off = 16; off > 0; off >>= 1)
            acc += __shfl_xor_sync(0xffffffffu, acc, off);

        if (lane == 0)
            out[b * SQ + s] = acc + bias[idx];
    }
}

extern "C" void kernel_launch(void* const* d_in, const int* in_sizes, int n_in,
                              void* d_out, int out_size) {
    const float* input     = (const float*)d_in[0];      // [B, D]
    const float* labels    = (const float*)d_in[1];      // [L, D]
    const float* weight    = (const float*)d_in[2];      // [L, D]
    const float* alpha     = (const float*)d_in[3];      // [1, D]
    const float* beta      = (const float*)d_in[4];      // [1, D]
    const float* bias      = (const float*)d_in[5];      // [L]
    const void*  shortlist = d_in[6];                    // [B, S] int32 or int64
    float*       out       = (float*)d_out;              // [B, S]

    const int B = in_sizes[0] / DQ;                 // 512
    const int blocks = B * (SQ / S_PER_BLOCK);      // 4096

    detect_idx_width_kernel<<<1, 256>>>((const unsigned long long*)shortlist);
    combine_uv_kernel<<<blocks, THREADS>>>(input, labels, weight, alpha, beta,
                                           bias, shortlist, out);
}

// round 7
// speedup vs baseline: 1.4432x; 1.4432x over previous
#include <cuda_runtime.h>

// Problem constants (from reference): L=131072, D=512, B=512, S=512
#define DQ 512
#define SQ 512

constexpr int WARPS_PER_BLOCK = 8;
constexpr int THREADS = WARPS_PER_BLOCK * 32;
constexpr int S_PER_BLOCK = 64;  // shortlist entries per block

__global__ __launch_bounds__(THREADS, 5)
void combine_uv_kernel(const float* __restrict__ input,    // [B, D]
                       const float* __restrict__ labels,   // [L, D]
                       const float* __restrict__ weight,   // [L, D]
                       const float* __restrict__ alpha,    // [1, D]
                       const float* __restrict__ beta,     // [1, D]
                       const float* __restrict__ bias,     // [L]
                       const void* __restrict__ shortlist, // [B, S] int32 or int64
                       float* __restrict__ out)            // [B, S]
{
    __shared__ float s_xa[DQ];
    __shared__ float s_xb[DQ];

    const int blocks_per_b = SQ / S_PER_BLOCK;   // 8
    const int b  = blockIdx.x / blocks_per_b;
    const int s0 = (blockIdx.x % blocks_per_b) * S_PER_BLOCK;
    const int tid  = threadIdx.x;
    const int warp = tid >> 5;
    const int lane = tid & 31;

    // ---- Inline shortlist dtype detection (no extra kernel) ----
    // int64 layout: all indices < 2^17 -> high word of every u64 is 0.
    // int32 layout: high word of u64 i is index (2i+1), uniform in [0,131072);
    // OR over 32 words is nonzero with prob 1 - 131072^-32. 256B read, L2-hot.
    const unsigned long long* slu = (const unsigned long long*)shortlist;
    unsigned int hi = (unsigned int)(slu[lane] >> 32);
    hi = __reduce_or_sync(0xffffffffu, hi);
    const bool is32 = (hi != 0u);

    const int*       sl32 = (const int*)shortlist;
    const long long* sl64 = (const long long*)shortlist;

    // Fold sigmoid(alpha)/sigmoid(beta) into this sample's input row once.
    for (int d = tid; d < DQ; d += THREADS) {
        float x  = input[b * DQ + d];
        float sa = 1.0f / (1.0f + __expf(-alpha[d]));
        float sb = 1.0f / (1.0f + __expf(-beta[d]));
        s_xa[d] = x * sa;
        s_xb[d] = x * sb;
    }
    __syncthreads();

    const float4* xa4 = reinterpret_cast<const float4*>(s_xa);
    const float4* xb4 = reinterpret_cast<const float4*>(s_xb);

    // Each warp walks its share of the 64 entries; per entry: gather two 2KB rows.
    for (int e = warp; e < S_PER_BLOCK; e += WARPS_PER_BLOCK) {
        const int s = s0 + e;
        const long long flat = (long long)b * SQ + s;
        const long long idx = is32 ? (long long)sl32[flat] : sl64[flat];

        const float4* w = reinterpret_cast<const float4*>(weight + idx * DQ);
        const float4* v = reinterpret_cast<const float4*>(labels + idx * DQ);

        // Issue all 16 independent 16B gathers before consuming -> max MLP.
        float4 w0 = w[lane], v0 = v[lane];
        float4 w1 = w[lane + 32], v1 = v[lane + 32];
        float4 w2 = w[lane + 64], v2 = v[lane + 64];
        float4 w3 = w[lane + 96], v3 = v[lane + 96];

        // Input read back from smem during the FMA phase (LDS latency hidden),
        // keeping registers free for outstanding gathers.
        float acc = (lane == 0) ? bias[idx] : 0.0f;
        float4 x0;
        x0 = xa4[lane];      acc += w0.x*x0.x + w0.y*x0.y + w0.z*x0.z + w0.w*x0.w;
        x0 = xb4[lane];      acc += v0.x*x0.x + v0.y*x0.y + v0.z*x0.z + v0.w*x0.w;
        x0 = xa4[lane + 32]; acc += w1.x*x0.x + w1.y*x0.y + w1.z*x0.z + w1.w*x0.w;
        x0 = xb4[lane + 32]; acc += v1.x*x0.x + v1.y*x0.y + v1.z*x0.z + v1.w*x0.w;
        x0 = xa4[lane + 64]; acc += w2.x*x0.x + w2.y*x0.y + w2.z*x0.z + w2.w*x0.w;
        x0 = xb4[lane + 64]; acc += v2.x*x0.x + v2.y*x0.y + v2.z*x0.z + v2.w*x0.w;
        x0 = xa4[lane + 96]; acc += w3.x*x0.x + w3.y*x0.y + w3.z*x0.z + w3.w*x0.w;
        x0 = xb4[lane + 96]; acc += v3.x*x0.x + v3.y*x0.y + v3.z*x0.z + v3.w*x0.w;

        // Warp tree reduction
        #pragma unroll
        for (int off = 16; off > 0; off >>= 1)
            acc += __shfl_xor_sync(0xffffffffu, acc, off);

        if (lane == 0)
            out[b * SQ + s] = acc;
    }
}

extern "C" void kernel_launch(void* const* d_in, const int* in_sizes, int n_in,
                              void* d_out, int out_size) {
    const float* input     = (const float*)d_in[0];      // [B, D]
    const float* labels    = (const float*)d_in[1];      // [L, D]
    const float* weight    = (const float*)d_in[2];      // [L, D]
    const float* alpha     = (const float*)d_in[3];      // [1, D]
    const float* beta      = (const float*)d_in[4];      // [1, D]
    const float* bias      = (const float*)d_in[5];      // [L]
    const void*  shortlist = d_in[6];                    // [B, S] int32 or int64
    float*       out       = (float*)d_out;              // [B, S]

    const int B = in_sizes[0] / DQ;                 // 512
    const int blocks = B * (SQ / S_PER_BLOCK);      // 4096

    combine_uv_kernel<<<blocks, THREADS>>>(input, labels, weight, alpha, beta,
                                           bias, shortlist, out);
}

// round 8
// speedup vs baseline: 1.6256x; 1.1264x over previous
#include <cuda_runtime.h>
#include <cuda_fp16.h>

// Problem constants (from reference): L=131072, D=512, B=512, S=512
#define LQ 131072
#define DQ 512
#define SQ 512

constexpr int WARPS_PER_BLOCK = 8;
constexpr int THREADS = WARPS_PER_BLOCK * 32;
constexpr int S_PER_BLOCK = 64;  // shortlist entries per block

// Combined fp16 table C[L,D] = sigmoid(alpha)*W + sigmoid(beta)*V  (128 MB scratch)
__device__ __half g_C[(size_t)LQ * DQ];

// ---------------------------------------------------------------------------
// Kernel 1: build C. One uint4 (8 halfs) per thread. Streaming, DRAM-bound.
// ---------------------------------------------------------------------------
__global__ __launch_bounds__(256)
void build_C_kernel(const float* __restrict__ W,      // weight [L, D]
                    const float* __restrict__ V,      // labels [L, D]
                    const float* __restrict__ alpha,  // [1, D]
                    const float* __restrict__ beta)   // [1, D]
{
    __shared__ float s_sa[DQ];
    __shared__ float s_sb[DQ];
    for (int d = threadIdx.x; d < DQ; d += 256) {
        s_sa[d] = 1.0f / (1.0f + __expf(-alpha[d]));
        s_sb[d] = 1.0f / (1.0f + __expf(-beta[d]));
    }
    __syncthreads();

    const long long u = (long long)blockIdx.x * 256 + threadIdx.x;  // 16B unit id
    const long long base = u * 8;                                    // element id
    const int d0 = (int)(base & (DQ - 1));

    const float4* w4 = reinterpret_cast<const float4*>(W + base);
    const float4* v4 = reinterpret_cast<const float4*>(V + base);
    float4 wa = w4[0], wb = w4[1];
    float4 va = v4[0], vb = v4[1];

    float r0 = s_sa[d0+0]*wa.x + s_sb[d0+0]*va.x;
    float r1 = s_sa[d0+1]*wa.y + s_sb[d0+1]*va.y;
    float r2 = s_sa[d0+2]*wa.z + s_sb[d0+2]*va.z;
    float r3 = s_sa[d0+3]*wa.w + s_sb[d0+3]*va.w;
    float r4 = s_sa[d0+4]*wb.x + s_sb[d0+4]*vb.x;
    float r5 = s_sa[d0+5]*wb.y + s_sb[d0+5]*vb.y;
    float r6 = s_sa[d0+6]*wb.z + s_sb[d0+6]*vb.z;
    float r7 = s_sa[d0+7]*wb.w + s_sb[d0+7]*vb.w;

    __half2 h0 = __floats2half2_rn(r0, r1);
    __half2 h1 = __floats2half2_rn(r2, r3);
    __half2 h2 = __floats2half2_rn(r4, r5);
    __half2 h3 = __floats2half2_rn(r6, r7);

    uint4 outv;
    outv.x = *reinterpret_cast<unsigned int*>(&h0);
    outv.y = *reinterpret_cast<unsigned int*>(&h1);
    outv.z = *reinterpret_cast<unsigned int*>(&h2);
    outv.w = *reinterpret_cast<unsigned int*>(&h3);
    reinterpret_cast<uint4*>(g_C)[u] = outv;
}

// ---------------------------------------------------------------------------
// Kernel 2: gather + dot. One warp per 2 shortlist entries per iteration.
// Per entry: one 1KB fp16 row of C (lane loads 2x16B), dot vs fp32 x in smem.
// ---------------------------------------------------------------------------
__device__ __forceinline__ float dot8(uint4 p, const float2* __restrict__ x2) {
    __half2 h0 = *reinterpret_cast<__half2*>(&p.x);
    __half2 h1 = *reinterpret_cast<__half2*>(&p.y);
    __half2 h2 = *reinterpret_cast<__half2*>(&p.z);
    __half2 h3 = *reinterpret_cast<__half2*>(&p.w);
    float2 f0 = __half22float2(h0), f1 = __half22float2(h1);
    float2 f2 = __half22float2(h2), f3 = __half22float2(h3);
    float2 x0 = x2[0], x1 = x2[1], x2v = x2[2], x3 = x2[3];
    float acc;
    acc  = f0.x * x0.x + f0.y * x0.y;
    acc += f1.x * x1.x + f1.y * x1.y;
    acc += f2.x * x2v.x + f2.y * x2v.y;
    acc += f3.x * x3.x + f3.y * x3.y;
    return acc;
}

__global__ __launch_bounds__(THREADS)
void gather_dot_kernel(const float* __restrict__ input,    // [B, D]
                       const float* __restrict__ bias,     // [L]
                       const void* __restrict__ shortlist, // [B, S] int32 or int64
                       float* __restrict__ out)            // [B, S]
{
    __shared__ float s_x[DQ];

    const int blocks_per_b = SQ / S_PER_BLOCK;   // 8
    const int b  = blockIdx.x / blocks_per_b;
    const int s0 = (blockIdx.x % blocks_per_b) * S_PER_BLOCK;
    const int tid  = threadIdx.x;
    const int warp = tid >> 5;
    const int lane = tid & 31;

    // Inline shortlist dtype detection: int64 indices are < 2^17 so every
    // u64 high word is 0; int32 packing puts a random index in the high word.
    const unsigned long long* slu = (const unsigned long long*)shortlist;
    unsigned int hi = (unsigned int)(slu[lane] >> 32);
    hi = __reduce_or_sync(0xffffffffu, hi);
    const bool is32 = (hi != 0u);
    const int*       sl32 = (const int*)shortlist;
    const long long* sl64 = (const long long*)shortlist;

    for (int d = tid; d < DQ; d += THREADS)
        s_x[d] = input[b * DQ + d];
    __syncthreads();

    const uint4* C4 = reinterpret_cast<const uint4*>(g_C);
    const float2* x2 = reinterpret_cast<const float2*>(s_x);

    // 8 entries per warp, processed 2 at a time -> 4 x 16B gathers in flight.
    #pragma unroll
    for (int e = 0; e < 8; e += 2) {
        const int s = s0 + warp * 8 + e;
        const long long flat = (long long)b * SQ + s;
        const long long idx0 = is32 ? (long long)sl32[flat]     : sl64[flat];
        const long long idx1 = is32 ? (long long)sl32[flat + 1] : sl64[flat + 1];

        // Row = 512 halfs = 64 uint4 units; lane covers units {lane, lane+32}.
        uint4 p0 = C4[idx0 * 64 + lane];
        uint4 p1 = C4[idx0 * 64 + lane + 32];
        uint4 q0 = C4[idx1 * 64 + lane];
        uint4 q1 = C4[idx1 * 64 + lane + 32];

        float acc0 = dot8(p0, x2 + lane * 4) + dot8(p1, x2 + (lane + 32) * 4);
        float acc1 = dot8(q0, x2 + lane * 4) + dot8(q1, x2 + (lane + 32) * 4);

        #pragma unroll
        for (int off = 16; off > 0; off >>= 1) {
            acc0 += __shfl_xor_sync(0xffffffffu, acc0, off);
            acc1 += __shfl_xor_sync(0xffffffffu, acc1, off);
        }

        if (lane == 0) {
            out[b * SQ + s]     = acc0 + bias[idx0];
            out[b * SQ + s + 1] = acc1 + bias[idx1];
        }
    }
}

extern "C" void kernel_launch(void* const* d_in, const int* in_sizes, int n_in,
                              void* d_out, int out_size) {
    const float* input     = (const float*)d_in[0];      // [B, D]
    const float* labels    = (const float*)d_in[1];      // [L, D]  (v)
    const float* weight    = (const float*)d_in[2];      // [L, D]  (u)
    const float* alpha     = (const float*)d_in[3];      // [1, D]
    const float* beta      = (const float*)d_in[4];      // [1, D]
    const float* bias      = (const float*)d_in[5];      // [L]
    const void*  shortlist = d_in[6];                    // [B, S] int32 or int64
    float*       out       = (float*)d_out;              // [B, S]

    const int B = in_sizes[0] / DQ;                 // 512

    // L*D/8 threads, 256 per block
    const int build_blocks = (LQ * (long long)DQ) / 8 / 256;   // 32768
    build_C_kernel<<<build_blocks, 256>>>(weight, labels, alpha, beta);

    const int gather_blocks = B * (SQ / S_PER_BLOCK);          // 4096
    gather_dot_kernel<<<gather_blocks, THREADS>>>(input, bias, shortlist, out);
}

// round 9
// speedup vs baseline: 1.9304x; 1.1875x over previous
#include <cuda_runtime.h>
#include <cuda_fp16.h>

// Problem constants (from reference): L=131072, D=512, B=512, S=512
#define LQ 131072
#define DQ 512
#define SQ 512

// ---- static scratch (no runtime allocation) ----
__device__ int    g_count [LQ];        // refs per label
__device__ int    g_scan  [LQ];        // block-local exclusive scan
__device__ int    g_offset[LQ];        // CSR row starts
__device__ int    g_cursor[LQ];        // scatter cursors
__device__ int    g_bsum  [128];       // per-block sums for scan
__device__ int    g_pairs [512 * 512]; // packed (b<<16)|s, CSR order
__device__ __half g_Xh    [512 * DQ];  // fp16 input rows (512 KB, L2-resident)
__device__ float  g_sa    [DQ];        // sigmoid(alpha)
__device__ float  g_sb    [DQ];        // sigmoid(beta)

// ---------------------------------------------------------------------------
// dtype detection helper (shortlist may be int32 or int64; indices < 2^17)
// ---------------------------------------------------------------------------
__device__ __forceinline__ bool detect_is32(const void* sl, int lane) {
    const unsigned long long* slu = (const unsigned long long*)sl;
    unsigned int hi = (unsigned int)(slu[lane] >> 32);
    hi = __reduce_or_sync(0xffffffffu, hi);
    return hi != 0u;
}

// ---------------------------------------------------------------------------
// Pre-pass kernels
// ---------------------------------------------------------------------------
__global__ void zero_count_kernel() {
    g_count[blockIdx.x * 256 + threadIdx.x] = 0;
}

__global__ void sig_xh_kernel(const float* __restrict__ input,   // [B, D]
                              const float* __restrict__ alpha,
                              const float* __restrict__ beta) {
    int t = blockIdx.x * 256 + threadIdx.x;
    if (t < DQ) {
        g_sa[t] = 1.0f / (1.0f + __expf(-alpha[t]));
        g_sb[t] = 1.0f / (1.0f + __expf(-beta[t]));
    }
    // 8 input elements per thread -> fp16
    const long long base = (long long)t * 8;
    const float4* x4 = reinterpret_cast<const float4*>(input + base);
    float4 a = x4[0], b = x4[1];
    __half2 h0 = __floats2half2_rn(a.x, a.y);
    __half2 h1 = __floats2half2_rn(a.z, a.w);
    __half2 h2 = __floats2half2_rn(b.x, b.y);
    __half2 h3 = __floats2half2_rn(b.z, b.w);
    uint4 o;
    o.x = *reinterpret_cast<unsigned int*>(&h0);
    o.y = *reinterpret_cast<unsigned int*>(&h1);
    o.z = *reinterpret_cast<unsigned int*>(&h2);
    o.w = *reinterpret_cast<unsigned int*>(&h3);
    reinterpret_cast<uint4*>(g_Xh)[t] = o;
}

__global__ void hist_kernel(const void* __restrict__ shortlist) {
    const int lane = threadIdx.x & 31;
    const bool is32 = detect_is32(shortlist, lane);
    const int t = blockIdx.x * 256 + threadIdx.x;   // flat (b,s)
    const int idx = is32 ? ((const int*)shortlist)[t]
                         : (int)((const long long*)shortlist)[t];
    atomicAdd(&g_count[idx], 1);
}

__global__ void scan1_kernel() {   // 128 blocks x 1024
    __shared__ int sm[1024];
    const int i = blockIdx.x * 1024 + threadIdx.x;
    const int v = g_count[i];
    sm[threadIdx.x] = v;
    __syncthreads();
    for (int o = 1; o < 1024; o <<= 1) {
        int t = (threadIdx.x >= o) ? sm[threadIdx.x - o] : 0;
        __syncthreads();
        sm[threadIdx.x] += t;
        __syncthreads();
    }
    g_scan[i] = sm[threadIdx.x] - v;  // exclusive
    if (threadIdx.x == 1023) g_bsum[blockIdx.x] = sm[1023];
}

__global__ void scan2_kernel() {   // 1 block x 128
    __shared__ int sm[128];
    const int v = g_bsum[threadIdx.x];
    sm[threadIdx.x] = v;
    __syncthreads();
    for (int o = 1; o < 128; o <<= 1) {
        int t = (threadIdx.x >= o) ? sm[threadIdx.x - o] : 0;
        __syncthreads();
        sm[threadIdx.x] += t;
        __syncthreads();
    }
    g_bsum[threadIdx.x] = sm[threadIdx.x] - v;  // exclusive
}

__global__ void scan3_kernel() {   // 128 blocks x 1024
    const int i = blockIdx.x * 1024 + threadIdx.x;
    const int o = g_scan[i] + g_bsum[blockIdx.x];
    g_offset[i] = o;
    g_cursor[i] = o;
}

__global__ void scatter_kernel(const void* __restrict__ shortlist) {
    const int lane = threadIdx.x & 31;
    const bool is32 = detect_is32(shortlist, lane);
    const int t = blockIdx.x * 256 + threadIdx.x;   // flat = b*SQ + s
    const int idx = is32 ? ((const int*)shortlist)[t]
                         : (int)((const long long*)shortlist)[t];
    const int pos = atomicAdd(&g_cursor[idx], 1);
    const int b = t >> 9;           // SQ = 512
    const int s = t & (SQ - 1);
    g_pairs[pos] = (b << 16) | s;
}

// ---------------------------------------------------------------------------
// Main kernel: warp per label row. Stream W,V once; push dots to referencing
// samples (fp16 input rows from L2).
// ---------------------------------------------------------------------------
__device__ __forceinline__ float dot4h(uint2 u, float4 c) {
    __half2 h0 = *reinterpret_cast<__half2*>(&u.x);
    __half2 h1 = *reinterpret_cast<__half2*>(&u.y);
    float2 f0 = __half22float2(h0), f1 = __half22float2(h1);
    return f0.x * c.x + f0.y * c.y + f1.x * c.z + f1.y * c.w;
}

__global__ __launch_bounds__(256)
void score_kernel(const float* __restrict__ W,     // weight [L, D]
                  const float* __restrict__ V,     // labels [L, D]
                  const float* __restrict__ bias,  // [L]
                  float* __restrict__ out)         // [B, S]
{
    const int row  = blockIdx.x * 8 + (threadIdx.x >> 5);
    const int lane = threadIdx.x & 31;

    const int cnt = g_count[row];
    if (cnt == 0) return;
    const int off = g_offset[row];

    // Stream this label's W and V rows (coalesced, HBM) and fold sigmoids
    // into a register-resident combined row c (16 floats per lane).
    const float4* w4  = reinterpret_cast<const float4*>(W + (size_t)row * DQ);
    const float4* v4  = reinterpret_cast<const float4*>(V + (size_t)row * DQ);
    const float4* sa4 = reinterpret_cast<const float4*>(g_sa);
    const float4* sb4 = reinterpret_cast<const float4*>(g_sb);

    float4 c0, c1, c2, c3;
    {
        float4 w0 = w4[lane], w1 = w4[lane + 32], w2 = w4[lane + 64], w3 = w4[lane + 96];
        float4 v0 = v4[lane], v1 = v4[lane + 32], v2 = v4[lane + 64], v3 = v4[lane + 96];
        float4 a0 = sa4[lane], a1 = sa4[lane + 32], a2 = sa4[lane + 64], a3 = sa4[lane + 96];
        float4 b0 = sb4[lane], b1 = sb4[lane + 32], b2 = sb4[lane + 64], b3 = sb4[lane + 96];
        c0 = make_float4(a0.x*w0.x + b0.x*v0.x, a0.y*w0.y + b0.y*v0.y,
                         a0.z*w0.z + b0.z*v0.z, a0.w*w0.w + b0.w*v0.w);
        c1 = make_float4(a1.x*w1.x + b1.x*v1.x, a1.y*w1.y + b1.y*v1.y,
                         a1.z*w1.z + b1.z*v1.z, a1.w*w1.w + b1.w*v1.w);
        c2 = make_float4(a2.x*w2.x + b2.x*v2.x, a2.y*w2.y + b2.y*v2.y,
                         a2.z*w2.z + b2.z*v2.z, a2.w*w2.w + b2.w*v2.w);
        c3 = make_float4(a3.x*w3.x + b3.x*v3.x, a3.y*w3.y + b3.y*v3.y,
                         a3.z*w3.z + b3.z*v3.z, a3.w*w3.w + b3.w*v3.w);
    }

    const float bs = bias[row];

    int i = 0;
    // 2-way unrolled over refs for L2-latency overlap
    for (; i + 2 <= cnt; i += 2) {
        const int p0 = g_pairs[off + i];
        const int p1 = g_pairs[off + i + 1];
        const int b0 = p0 >> 16, s0 = p0 & 0xffff;
        const int b1 = p1 >> 16, s1 = p1 & 0xffff;
        const uint2* x0 = reinterpret_cast<const uint2*>(g_Xh + (size_t)b0 * DQ);
        const uint2* x1 = reinterpret_cast<const uint2*>(g_Xh + (size_t)b1 * DQ);

        uint2 u00 = x0[lane], u01 = x0[lane + 32], u02 = x0[lane + 64], u03 = x0[lane + 96];
        uint2 u10 = x1[lane], u11 = x1[lane + 32], u12 = x1[lane + 64], u13 = x1[lane + 96];

        float a0 = dot4h(u00, c0) + dot4h(u01, c1) + dot4h(u02, c2) + dot4h(u03, c3);
        float a1 = dot4h(u10, c0) + dot4h(u11, c1) + dot4h(u12, c2) + dot4h(u13, c3);

        #pragma unroll
        for (int o = 16; o > 0; o >>= 1) {
            a0 += __shfl_xor_sync(0xffffffffu, a0, o);
            a1 += __shfl_xor_sync(0xffffffffu, a1, o);
        }
        if (lane == 0) {
            out[b0 * SQ + s0] = a0 + bs;
            out[b1 * SQ + s1] = a1 + bs;
        }
    }
    if (i < cnt) {
        const int p0 = g_pairs[off + i];
        const int b0 = p0 >> 16, s0 = p0 & 0xffff;
        const uint2* x0 = reinterpret_cast<const uint2*>(g_Xh + (size_t)b0 * DQ);
        uint2 u00 = x0[lane], u01 = x0[lane + 32], u02 = x0[lane + 64], u03 = x0[lane + 96];
        float a0 = dot4h(u00, c0) + dot4h(u01, c1) + dot4h(u02, c2) + dot4h(u03, c3);
        #pragma unroll
        for (int o = 16; o > 0; o >>= 1)
            a0 += __shfl_xor_sync(0xffffffffu, a0, o);
        if (lane == 0)
            out[b0 * SQ + s0] = a0 + bs;
    }
}

extern "C" void kernel_launch(void* const* d_in, const int* in_sizes, int n_in,
                              void* d_out, int out_size) {
    const float* input     = (const float*)d_in[0];      // [B, D]
    const float* labels    = (const float*)d_in[1];      // [L, D]  (v)
    const float* weight    = (const float*)d_in[2];      // [L, D]  (u)
    const float* alpha     = (const float*)d_in[3];      // [1, D]
    const float* beta      = (const float*)d_in[4];      // [1, D]
    const float* bias      = (const float*)d_in[5];      // [L]
    const void*  shortlist = d_in[6];                    // [B, S] int32 or int64
    float*       out       = (float*)d_out;              // [B, S]

    const int B = in_sizes[0] / DQ;   // 512
    const int BS = B * SQ;            // 262144

    zero_count_kernel<<<LQ / 256, 256>>>();
    sig_xh_kernel<<<(B * DQ / 8) / 256, 256>>>(input, alpha, beta);
    hist_kernel<<<BS / 256, 256>>>(shortlist);
    scan1_kernel<<<128, 1024>>>();
    scan2_kernel<<<1, 128>>>();
    scan3_kernel<<<128, 1024>>>();
    scatter_kernel<<<BS / 256, 256>>>(shortlist);
    score_kernel<<<LQ / 8, 256>>>(weight, labels, bias, out);
}

// round 10
// speedup vs baseline: 2.0784x; 1.0767x over previous
#include <cuda_runtime.h>
#include <cuda_fp16.h>

// Problem constants (from reference): L=131072, D=512, B=512, S=512
#define LQ 131072
#define DQ 512
#define SQ 512
#define CAP 24          // slots per label row; Poisson(2) => P(cnt>24) ~ 1e-18
#define OVER_MAX 4096

// ---- static scratch (no runtime allocation) ----
__device__ int    g_count[LQ];          // refs per label
__device__ int    g_slots[(size_t)LQ * CAP];  // packed (b<<16)|s per label
__device__ int    g_over [OVER_MAX * 2];      // overflow {row, pair}
__device__ int    g_over_n;
__device__ __half g_Xh   [512 * DQ];    // fp16 input rows (512 KB, L2-resident)
__device__ float  g_sa   [DQ];          // sigmoid(alpha)
__device__ float  g_sb   [DQ];          // sigmoid(beta)

// ---------------------------------------------------------------------------
// dtype detection (shortlist may be int32 or int64; true indices < 2^17 so
// int64 high words are all zero; int32 packing puts a random index there)
// ---------------------------------------------------------------------------
__device__ __forceinline__ bool detect_is32(const void* sl, int lane) {
    const unsigned long long* slu = (const unsigned long long*)sl;
    unsigned int hi = (unsigned int)(slu[lane] >> 32);
    hi = __reduce_or_sync(0xffffffffu, hi);
    return hi != 0u;
}

// ---------------------------------------------------------------------------
// Kernel A: zero counts/overflow + sigmoid LUTs + fp16 input rows.
// blocks [0,128): zero g_count (int4). blocks [128,256): sig + Xh.
// ---------------------------------------------------------------------------
__global__ __launch_bounds__(256)
void init_kernel(const float* __restrict__ input,
                 const float* __restrict__ alpha,
                 const float* __restrict__ beta) {
    const int bid = blockIdx.x;
    if (bid < 128) {
        const int t = bid * 256 + threadIdx.x;          // 32768 int4 = 131072 ints
        reinterpret_cast<int4*>(g_count)[t] = make_int4(0, 0, 0, 0);
        if (bid == 0 && threadIdx.x == 0) g_over_n = 0;
        return;
    }
    const int t = (bid - 128) * 256 + threadIdx.x;      // 32768 threads
    if (t < DQ) {
        g_sa[t] = 1.0f / (1.0f + __expf(-alpha[t]));
        g_sb[t] = 1.0f / (1.0f + __expf(-beta[t]));
    }
    const long long base = (long long)t * 8;            // 8 floats -> 8 halfs
    const float4* x4 = reinterpret_cast<const float4*>(input + base);
    float4 a = x4[0], b = x4[1];
    __half2 h0 = __floats2half2_rn(a.x, a.y);
    __half2 h1 = __floats2half2_rn(a.z, a.w);
    __half2 h2 = __floats2half2_rn(b.x, b.y);
    __half2 h3 = __floats2half2_rn(b.z, b.w);
    uint4 o;
    o.x = *reinterpret_cast<unsigned int*>(&h0);
    o.y = *reinterpret_cast<unsigned int*>(&h1);
    o.z = *reinterpret_cast<unsigned int*>(&h2);
    o.w = *reinterpret_cast<unsigned int*>(&h3);
    reinterpret_cast<uint4*>(g_Xh)[t] = o;
}

// ---------------------------------------------------------------------------
// Kernel B: one-pass bucket build (replaces hist + scan x3 + scatter).
// ---------------------------------------------------------------------------
__global__ __launch_bounds__(256)
void bucket_kernel(const void* __restrict__ shortlist) {
    const int lane = threadIdx.x & 31;
    const bool is32 = detect_is32(shortlist, lane);
    const int t = blockIdx.x * 256 + threadIdx.x;       // flat = b*SQ + s
    const int idx = is32 ? ((const int*)shortlist)[t]
                         : (int)((const long long*)shortlist)[t];
    const int pair = ((t >> 9) << 16) | (t & (SQ - 1)); // (b<<16)|s
    const int pos = atomicAdd(&g_count[idx], 1);
    if (pos < CAP) {
        g_slots[(size_t)idx * CAP + pos] = pair;
    } else {
        const int o = atomicAdd(&g_over_n, 1);
        if (o < OVER_MAX) { g_over[o * 2] = idx; g_over[o * 2 + 1] = pair; }
    }
}

// ---------------------------------------------------------------------------
// Kernel C: warp per label row. Stream W,V once (HBM); push dots to
// referencing samples (fp16 input rows from L2).
// ---------------------------------------------------------------------------
__device__ __forceinline__ float dot4h(uint2 u, float4 c) {
    __half2 h0 = *reinterpret_cast<__half2*>(&u.x);
    __half2 h1 = *reinterpret_cast<__half2*>(&u.y);
    float2 f0 = __half22float2(h0), f1 = __half22float2(h1);
    return f0.x * c.x + f0.y * c.y + f1.x * c.z + f1.y * c.w;
}

__global__ __launch_bounds__(256)
void score_kernel(const float* __restrict__ W,     // weight [L, D]
                  const float* __restrict__ V,     // labels [L, D]
                  const float* __restrict__ bias,  // [L]
                  float* __restrict__ out)         // [B, S]
{
    const int row  = blockIdx.x * 8 + (threadIdx.x >> 5);
    const int lane = threadIdx.x & 31;

    int cnt = g_count[row];
    if (cnt == 0) return;
    if (cnt > CAP) cnt = CAP;            // overflow refs handled separately
    const int* slots = g_slots + (size_t)row * CAP;

    // Hoist the first two pair words: independent of the W/V DRAM stream, so
    // the pair->Xh L2 chain overlaps the 577-cycle row fetch.
    int p0 = slots[0];
    int p1 = (cnt > 1) ? slots[1] : 0;

    const float4* w4  = reinterpret_cast<const float4*>(W + (size_t)row * DQ);
    const float4* v4  = reinterpret_cast<const float4*>(V + (size_t)row * DQ);
    const float4* sa4 = reinterpret_cast<const float4*>(g_sa);
    const float4* sb4 = reinterpret_cast<const float4*>(g_sb);

    float4 c0, c1, c2, c3;
    {
        float4 w0 = w4[lane], w1 = w4[lane + 32], w2 = w4[lane + 64], w3 = w4[lane + 96];
        float4 v0 = v4[lane], v1 = v4[lane + 32], v2 = v4[lane + 64], v3 = v4[lane + 96];
        float4 a0 = sa4[lane], a1 = sa4[lane + 32], a2 = sa4[lane + 64], a3 = sa4[lane + 96];
        float4 b0 = sb4[lane], b1 = sb4[lane + 32], b2 = sb4[lane + 64], b3 = sb4[lane + 96];
        c0 = make_float4(a0.x*w0.x + b0.x*v0.x, a0.y*w0.y + b0.y*v0.y,
                         a0.z*w0.z + b0.z*v0.z, a0.w*w0.w + b0.w*v0.w);
        c1 = make_float4(a1.x*w1.x + b1.x*v1.x, a1.y*w1.y + b1.y*v1.y,
                         a1.z*w1.z + b1.z*v1.z, a1.w*w1.w + b1.w*v1.w);
        c2 = make_float4(a2.x*w2.x + b2.x*v2.x, a2.y*w2.y + b2.y*v2.y,
                         a2.z*w2.z + b2.z*v2.z, a2.w*w2.w + b2.w*v2.w);
        c3 = make_float4(a3.x*w3.x + b3.x*v3.x, a3.y*w3.y + b3.y*v3.y,
                         a3.z*w3.z + b3.z*v3.z, a3.w*w3.w + b3.w*v3.w);
    }

    const float bs = bias[row];

    int i = 0;
    for (; i + 2 <= cnt; i += 2) {
        const int b0 = p0 >> 16, s0 = p0 & 0xffff;
        const int b1 = p1 >> 16, s1 = p1 & 0xffff;
        const uint2* x0 = reinterpret_cast<const uint2*>(g_Xh + (size_t)b0 * DQ);
        const uint2* x1 = reinterpret_cast<const uint2*>(g_Xh + (size_t)b1 * DQ);

        uint2 u00 = x0[lane], u01 = x0[lane + 32], u02 = x0[lane + 64], u03 = x0[lane + 96];
        uint2 u10 = x1[lane], u11 = x1[lane + 32], u12 = x1[lane + 64], u13 = x1[lane + 96];

        // prefetch next pair words
        if (i + 2 < cnt) {
            p0 = slots[i + 2];
            p1 = (i + 3 < cnt) ? slots[i + 3] : 0;
        }

        float a0 = dot4h(u00, c0) + dot4h(u01, c1) + dot4h(u02, c2) + dot4h(u03, c3);
        float a1 = dot4h(u10, c0) + dot4h(u11, c1) + dot4h(u12, c2) + dot4h(u13, c3);

        #pragma unroll
        for (int o = 16; o > 0; o >>= 1) {
            a0 += __shfl_xor_sync(0xffffffffu, a0, o);
            a1 += __shfl_xor_sync(0xffffffffu, a1, o);
        }
        if (lane == 0) {
            out[b0 * SQ + s0] = a0 + bs;
            out[b1 * SQ + s1] = a1 + bs;
        }
    }
    if (i < cnt) {
        const int b0 = p0 >> 16, s0 = p0 & 0xffff;
        const uint2* x0 = reinterpret_cast<const uint2*>(g_Xh + (size_t)b0 * DQ);
        uint2 u00 = x0[lane], u01 = x0[lane + 32], u02 = x0[lane + 64], u03 = x0[lane + 96];
        float a0 = dot4h(u00, c0) + dot4h(u01, c1) + dot4h(u02, c2) + dot4h(u03, c3);
        #pragma unroll
        for (int o = 16; o > 0; o >>= 1)
            a0 += __shfl_xor_sync(0xffffffffu, a0, o);
        if (lane == 0)
            out[b0 * SQ + s0] = a0 + bs;
    }
}

// ---------------------------------------------------------------------------
// Kernel D: overflow cleanup (expected 0 entries; correctness safety net).
// One warp per overflow ref, gather-style.
// ---------------------------------------------------------------------------
__global__ __launch_bounds__(256)
void overflow_kernel(const float* __restrict__ W,
                     const float* __restrict__ V,
                     const float* __restrict__ bias,
                     float* __restrict__ out) {
    const int lane = threadIdx.x & 31;
    const int warp = threadIdx.x >> 5;
    int n = g_over_n;
    if (n > OVER_MAX) n = OVER_MAX;
    for (int i = warp; i < n; i += 8) {
        const int row  = g_over[i * 2];
        const int pair = g_over[i * 2 + 1];
        const int b = pair >> 16, s = pair & 0xffff;
        const float4* w4  = reinterpret_cast<const float4*>(W + (size_t)row * DQ);
        const float4* v4  = reinterpret_cast<const float4*>(V + (size_t)row * DQ);
        const float4* sa4 = reinterpret_cast<const float4*>(g_sa);
        const float4* sb4 = reinterpret_cast<const float4*>(g_sb);
        const uint2*  x2  = reinterpret_cast<const uint2*>(g_Xh + (size_t)b * DQ);
        float acc = 0.0f;
        #pragma unroll
        for (int k = 0; k < 4; k++) {
            float4 w = w4[lane + 32 * k], v = v4[lane + 32 * k];
            float4 a = sa4[lane + 32 * k], bb = sb4[lane + 32 * k];
            float4 c = make_float4(a.x*w.x + bb.x*v.x, a.y*w.y + bb.y*v.y,
                                   a.z*w.z + bb.z*v.z, a.w*w.w + bb.w*v.w);
            acc += dot4h(x2[lane + 32 * k], c);
        }
        #pragma unroll
        for (int o = 16; o > 0; o >>= 1)
            acc += __shfl_xor_sync(0xffffffffu, acc, o);
        if (lane == 0)
            out[b * SQ + s] = acc + bias[row];
    }
}

extern "C" void kernel_launch(void* const* d_in, const int* in_sizes, int n_in,
                              void* d_out, int out_size) {
    const float* input     = (const float*)d_in[0];      // [B, D]
    const float* labels    = (const float*)d_in[1];      // [L, D]  (v)
    const float* weight    = (const float*)d_in[2];      // [L, D]  (u)
    const float* alpha     = (const float*)d_in[3];      // [1, D]
    const float* beta      = (const float*)d_in[4];      // [1, D]
    const float* bias      = (const float*)d_in[5];      // [L]
    const void*  shortlist = d_in[6];                    // [B, S] int32 or int64
    float*       out       = (float*)d_out;              // [B, S]

    const int B = in_sizes[0] / DQ;   // 512
    const int BS = B * SQ;            // 262144

    init_kernel<<<256, 256>>>(input, alpha, beta);
    bucket_kernel<<<BS / 256, 256>>>(shortlist);
    score_kernel<<<LQ / 8, 256>>>(weight, labels, bias, out);
    overflow_kernel<<<1, 256>>>(weight, labels, bias, out);
}

// round 11
// speedup vs baseline: 2.2338x; 1.0748x over previous
#include <cuda_runtime.h>
#include <cuda_fp16.h>

// Problem constants (from reference): L=131072, D=512, B=512, S=512
#define LQ 131072
#define DQ 512
#define SQ 512
#define CAP 24          // slots per label row; Poisson(2) => P(cnt>24) ~ 1e-18

// ---- static scratch (no runtime allocation; zero-initialized at load) ----
// g_count is SELF-CLEANING: score_kernel resets each row to 0 after reading,
// so every kernel_launch invocation (and every graph replay) starts from zeros.
__device__ int    g_count[LQ];                // refs per label
__device__ int    g_slots[(size_t)LQ * CAP];  // packed (b<<16)|s per label
__device__ __half g_Xh   [512 * DQ];          // fp16 input rows (512 KB, L2-resident)
__device__ float  g_sa   [DQ];                // sigmoid(alpha)
__device__ float  g_sb   [DQ];                // sigmoid(beta)

// ---------------------------------------------------------------------------
// dtype detection (shortlist may be int32 or int64; true indices < 2^17 so
// int64 high words are all zero; int32 packing puts a random index there)
// ---------------------------------------------------------------------------
__device__ __forceinline__ bool detect_is32(const void* sl, int lane) {
    const unsigned long long* slu = (const unsigned long long*)sl;
    unsigned int hi = (unsigned int)(slu[lane] >> 32);
    hi = __reduce_or_sync(0xffffffffu, hi);
    return hi != 0u;
}

// ---------------------------------------------------------------------------
// Kernel A (prep): blocks [0,1024) bucket the shortlist into per-label slots;
// blocks [1024,1152) build sigmoid LUTs + fp16 input rows.
// ---------------------------------------------------------------------------
__global__ __launch_bounds__(256)
void prep_kernel(const void* __restrict__ shortlist,
                 const float* __restrict__ input,
                 const float* __restrict__ alpha,
                 const float* __restrict__ beta) {
    const int bid = blockIdx.x;
    if (bid < 1024) {
        const int lane = threadIdx.x & 31;
        const bool is32 = detect_is32(shortlist, lane);
        const int t = bid * 256 + threadIdx.x;       // flat = b*SQ + s
        const int idx = is32 ? ((const int*)shortlist)[t]
                             : (int)((const long long*)shortlist)[t];
        const int pair = ((t >> 9) << 16) | (t & (SQ - 1)); // (b<<16)|s
        const int pos = atomicAdd(&g_count[idx], 1);
        if (pos < CAP)
            g_slots[(size_t)idx * CAP + pos] = pair;
        // cnt > CAP rows are recomputed from the shortlist in score_kernel.
        return;
    }
    const int t = (bid - 1024) * 256 + threadIdx.x;  // 32768 threads
    if (t < DQ) {
        g_sa[t] = 1.0f / (1.0f + __expf(-alpha[t]));
        g_sb[t] = 1.0f / (1.0f + __expf(-beta[t]));
    }
    const long long base = (long long)t * 8;         // 8 floats -> 8 halfs
    const float4* x4 = reinterpret_cast<const float4*>(input + base);
    float4 a = x4[0], b = x4[1];
    __half2 h0 = __floats2half2_rn(a.x, a.y);
    __half2 h1 = __floats2half2_rn(a.z, a.w);
    __half2 h2 = __floats2half2_rn(b.x, b.y);
    __half2 h3 = __floats2half2_rn(b.z, b.w);
    uint4 o;
    o.x = *reinterpret_cast<unsigned int*>(&h0);
    o.y = *reinterpret_cast<unsigned int*>(&h1);
    o.z = *reinterpret_cast<unsigned int*>(&h2);
    o.w = *reinterpret_cast<unsigned int*>(&h3);
    reinterpret_cast<uint4*>(g_Xh)[t] = o;
}

// ---------------------------------------------------------------------------
// Kernel B (score): warp per label row. Stream W,V once (HBM), fold sigmoids
// into a register-resident combined row, push dots to referencing samples
// (fp16 input rows from L2). Self-cleans g_count.
// ---------------------------------------------------------------------------
__device__ __forceinline__ float dot4h(uint2 u, float4 c) {
    __half2 h0 = *reinterpret_cast<__half2*>(&u.x);
    __half2 h1 = *reinterpret_cast<__half2*>(&u.y);
    float2 f0 = __half22float2(h0), f1 = __half22float2(h1);
    return f0.x * c.x + f0.y * c.y + f1.x * c.z + f1.y * c.w;
}

__global__ __launch_bounds__(256, 6)
void score_kernel(const float* __restrict__ W,       // weight [L, D]
                  const float* __restrict__ V,       // labels [L, D]
                  const float* __restrict__ bias,    // [L]
                  const void*  __restrict__ shortlist,
                  float* __restrict__ out)           // [B, S]
{
    const int row  = blockIdx.x * 8 + (threadIdx.x >> 5);
    const int lane = threadIdx.x & 31;

    const int cnt = g_count[row];
    if (lane == 0 && cnt != 0) g_count[row] = 0;   // self-clean for next launch
    if (cnt == 0) return;

    const int* slots = g_slots + (size_t)row * CAP;

    // Hoist first pair words: independent of the W/V DRAM stream, so the
    // pair -> Xh L2 chain overlaps the long row fetch.
    int p0 = slots[0];
    int p1 = (cnt > 1) ? slots[1] : 0;

    const float4* w4  = reinterpret_cast<const float4*>(W + (size_t)row * DQ);
    const float4* v4  = reinterpret_cast<const float4*>(V + (size_t)row * DQ);
    const float4* sa4 = reinterpret_cast<const float4*>(g_sa);
    const float4* sb4 = reinterpret_cast<const float4*>(g_sb);

    float4 c0, c1, c2, c3;
    {
        float4 w0 = w4[lane], w1 = w4[lane + 32], w2 = w4[lane + 64], w3 = w4[lane + 96];
        float4 v0 = v4[lane], v1 = v4[lane + 32], v2 = v4[lane + 64], v3 = v4[lane + 96];
        float4 a0 = sa4[lane], a1 = sa4[lane + 32], a2 = sa4[lane + 64], a3 = sa4[lane + 96];
        float4 b0 = sb4[lane], b1 = sb4[lane + 32], b2 = sb4[lane + 64], b3 = sb4[lane + 96];
        c0 = make_float4(a0.x*w0.x + b0.x*v0.x, a0.y*w0.y + b0.y*v0.y,
                         a0.z*w0.z + b0.z*v0.z, a0.w*w0.w + b0.w*v0.w);
        c1 = make_float4(a1.x*w1.x + b1.x*v1.x, a1.y*w1.y + b1.y*v1.y,
                         a1.z*w1.z + b1.z*v1.z, a1.w*w1.w + b1.w*v1.w);
        c2 = make_float4(a2.x*w2.x + b2.x*v2.x, a2.y*w2.y + b2.y*v2.y,
                         a2.z*w2.z + b2.z*v2.z, a2.w*w2.w + b2.w*v2.w);
        c3 = make_float4(a3.x*w3.x + b3.x*v3.x, a3.y*w3.y + b3.y*v3.y,
                         a3.z*w3.z + b3.z*v3.z, a3.w*w3.w + b3.w*v3.w);
    }

    const float bs = bias[row];

    if (cnt <= CAP) {
        int i = 0;
        for (; i + 2 <= cnt; i += 2) {
            const int b0 = p0 >> 16, s0 = p0 & 0xffff;
            const int b1 = p1 >> 16, s1 = p1 & 0xffff;
            const uint2* x0 = reinterpret_cast<const uint2*>(g_Xh + (size_t)b0 * DQ);
            const uint2* x1 = reinterpret_cast<const uint2*>(g_Xh + (size_t)b1 * DQ);

            uint2 u00 = x0[lane], u01 = x0[lane + 32], u02 = x0[lane + 64], u03 = x0[lane + 96];
            uint2 u10 = x1[lane], u11 = x1[lane + 32], u12 = x1[lane + 64], u13 = x1[lane + 96];

            if (i + 2 < cnt) {                       // prefetch next pair words
                p0 = slots[i + 2];
                p1 = (i + 3 < cnt) ? slots[i + 3] : 0;
            }

            float a0 = dot4h(u00, c0) + dot4h(u01, c1) + dot4h(u02, c2) + dot4h(u03, c3);
            float a1 = dot4h(u10, c0) + dot4h(u11, c1) + dot4h(u12, c2) + dot4h(u13, c3);

            #pragma unroll
            for (int o = 16; o > 0; o >>= 1) {
                a0 += __shfl_xor_sync(0xffffffffu, a0, o);
                a1 += __shfl_xor_sync(0xffffffffu, a1, o);
            }
            if (lane == 0) {
                out[b0 * SQ + s0] = a0 + bs;
                out[b1 * SQ + s1] = a1 + bs;
            }
        }
        if (i < cnt) {
            const int b0 = p0 >> 16, s0 = p0 & 0xffff;
            const uint2* x0 = reinterpret_cast<const uint2*>(g_Xh + (size_t)b0 * DQ);
            uint2 u00 = x0[lane], u01 = x0[lane + 32], u02 = x0[lane + 64], u03 = x0[lane + 96];
            float a0 = dot4h(u00, c0) + dot4h(u01, c1) + dot4h(u02, c2) + dot4h(u03, c3);
            #pragma unroll
            for (int o = 16; o > 0; o >>= 1)
                a0 += __shfl_xor_sync(0xffffffffu, a0, o);
            if (lane == 0)
                out[b0 * SQ + s0] = a0 + bs;
        }
    } else {
        // Overflow safety net (statistically never taken): the stored slot
        // subset is nondeterministic, so recompute ALL refs of this row by
        // rescanning the shortlist. Each ref's output is independent.
        const bool is32 = detect_is32(shortlist, lane);
        const int*       sl32 = (const int*)shortlist;
        const long long* sl64 = (const long long*)shortlist;
        #pragma unroll 1
        for (int t = 0; t < 512 * SQ; t++) {
            const int idx = is32 ? sl32[t] : (int)sl64[t];
            if (idx != row) continue;
            const int b0 = t >> 9, s0 = t & (SQ - 1);
            const uint2* x0 = reinterpret_cast<const uint2*>(g_Xh + (size_t)b0 * DQ);
            uint2 u00 = x0[lane], u01 = x0[lane + 32], u02 = x0[lane + 64], u03 = x0[lane + 96];
            float a0 = dot4h(u00, c0) + dot4h(u01, c1) + dot4h(u02, c2) + dot4h(u03, c3);
            #pragma unroll
            for (int o = 16; o > 0; o >>= 1)
                a0 += __shfl_xor_sync(0xffffffffu, a0, o);
            if (lane == 0)
                out[b0 * SQ + s0] = a0 + bs;
        }
    }
}

extern "C" void kernel_launch(void* const* d_in, const int* in_sizes, int n_in,
                              void* d_out, int out_size) {
    const float* input     = (const float*)d_in[0];      // [B, D]
    const float* labels    = (const float*)d_in[1];      // [L, D]  (v)
    const float* weight    = (const float*)d_in[2];      // [L, D]  (u)
    const float* alpha     = (const float*)d_in[3];      // [1, D]
    const float* beta      = (const float*)d_in[4];      // [1, D]
    const float* bias      = (const float*)d_in[5];      // [L]
    const void*  shortlist = d_in[6];                    // [B, S] int32 or int64
    float*       out       = (float*)d_out;              // [B, S]

    prep_kernel<<<1152, 256>>>(shortlist, input, alpha, beta);
    score_kernel<<<LQ / 8, 256>>>(weight, labels, bias, shortlist, out);
}

// round 12
// speedup vs baseline: 2.3705x; 1.0612x over previous
#include <cuda_runtime.h>
#include <cuda_fp16.h>

// Problem constants (from reference): L=131072, D=512, B=512, S=512
#define LQ 131072
#define DQ 512
#define SQ 512
#define CAP 24          // slots per label row; Poisson(2) => P(cnt>24) ~ 1e-18

// ---- static scratch (no runtime allocation; zero-initialized at load) ----
// g_count is SELF-CLEANING: score_kernel resets each row to 0 after reading,
// so every kernel_launch invocation (and every graph replay) starts from zeros.
__device__ int    g_count[LQ];                // refs per label
__device__ int    g_slots[(size_t)LQ * CAP];  // packed (b<<16)|s per label
__device__ __half g_Xh   [512 * DQ];          // fp16 input rows (512 KB, L2-resident)
__device__ float  g_sa   [DQ];                // sigmoid(alpha)
__device__ float  g_sb   [DQ];                // sigmoid(beta)

// ---------------------------------------------------------------------------
// dtype detection (shortlist may be int32 or int64; true indices < 2^17 so
// int64 high words are all zero; int32 packing puts a random index there)
// ---------------------------------------------------------------------------
__device__ __forceinline__ bool detect_is32(const void* sl, int lane) {
    const unsigned long long* slu = (const unsigned long long*)sl;
    unsigned int hi = (unsigned int)(slu[lane] >> 32);
    hi = __reduce_or_sync(0xffffffffu, hi);
    return hi != 0u;
}

// ---------------------------------------------------------------------------
// Kernel A (prep): blocks [0,1024) bucket the shortlist into per-label slots;
// blocks [1024,1152) build sigmoid LUTs + fp16 input rows.
// ---------------------------------------------------------------------------
__global__ __launch_bounds__(256)
void prep_kernel(const void* __restrict__ shortlist,
                 const float* __restrict__ input,
                 const float* __restrict__ alpha,
                 const float* __restrict__ beta) {
    const int bid = blockIdx.x;
    if (bid < 1024) {
        const int lane = threadIdx.x & 31;
        const bool is32 = detect_is32(shortlist, lane);
        const int t = bid * 256 + threadIdx.x;       // flat = b*SQ + s
        const int idx = is32 ? ((const int*)shortlist)[t]
                             : (int)((const long long*)shortlist)[t];
        const int pair = ((t >> 9) << 16) | (t & (SQ - 1)); // (b<<16)|s
        const int pos = atomicAdd(&g_count[idx], 1);
        if (pos < CAP)
            g_slots[(size_t)idx * CAP + pos] = pair;
        // cnt > CAP rows are recomputed from the shortlist in score_kernel.
        return;
    }
    const int t = (bid - 1024) * 256 + threadIdx.x;  // 32768 threads
    if (t < DQ) {
        g_sa[t] = 1.0f / (1.0f + __expf(-alpha[t]));
        g_sb[t] = 1.0f / (1.0f + __expf(-beta[t]));
    }
    const long long base = (long long)t * 8;         // 8 floats -> 8 halfs
    const float4* x4 = reinterpret_cast<const float4*>(input + base);
    float4 a = x4[0], b = x4[1];
    __half2 h0 = __floats2half2_rn(a.x, a.y);
    __half2 h1 = __floats2half2_rn(a.z, a.w);
    __half2 h2 = __floats2half2_rn(b.x, b.y);
    __half2 h3 = __floats2half2_rn(b.z, b.w);
    uint4 o;
    o.x = *reinterpret_cast<unsigned int*>(&h0);
    o.y = *reinterpret_cast<unsigned int*>(&h1);
    o.z = *reinterpret_cast<unsigned int*>(&h2);
    o.w = *reinterpret_cast<unsigned int*>(&h3);
    reinterpret_cast<uint4*>(g_Xh)[t] = o;
}

// ---------------------------------------------------------------------------
// Kernel B (score): warp per label row. Stream W,V once (HBM, evict-first),
// fold sigmoids into a register-resident combined row, push dots to
// referencing samples (fp16 input rows from L1/L2). Self-cleans g_count.
// ---------------------------------------------------------------------------
__device__ __forceinline__ float dot4h(uint2 u, float4 c) {
    __half2 h0 = *reinterpret_cast<__half2*>(&u.x);
    __half2 h1 = *reinterpret_cast<__half2*>(&u.y);
    float2 f0 = __half22float2(h0), f1 = __half22float2(h1);
    return f0.x * c.x + f0.y * c.y + f1.x * c.z + f1.y * c.w;
}

__global__ __launch_bounds__(256, 6)
void score_kernel(const float* __restrict__ W,       // weight [L, D]
                  const float* __restrict__ V,       // labels [L, D]
                  const float* __restrict__ bias,    // [L]
                  const void*  __restrict__ shortlist,
                  float* __restrict__ out)           // [B, S]
{
    const int row  = blockIdx.x * 8 + (threadIdx.x >> 5);
    const int lane = threadIdx.x & 31;

    const int cnt = g_count[row];
    if (lane == 0 && cnt != 0) g_count[row] = 0;   // self-clean for next launch
    if (cnt == 0) return;

    const int* slots = g_slots + (size_t)row * CAP;

    // Hoist first pair words: independent of the W/V DRAM stream, so the
    // pair -> Xh chain overlaps the long row fetch.
    int p0 = slots[0];
    int p1 = (cnt > 1) ? slots[1] : 0;

    const float4* w4  = reinterpret_cast<const float4*>(W + (size_t)row * DQ);
    const float4* v4  = reinterpret_cast<const float4*>(V + (size_t)row * DQ);
    const float4* sa4 = reinterpret_cast<const float4*>(g_sa);
    const float4* sb4 = reinterpret_cast<const float4*>(g_sb);

    // Interleave DRAM batches (4 LDG.128) with L1-hit LUT loads: shortens the
    // consecutive front-batched LDG run (spread mitigation), keeps 8 DRAM
    // loads in flight quickly. W/V are read-once -> __ldcs (evict-first, no
    // L1 pollution of the hot Xh working set).
    float4 w0 = __ldcs(w4 + lane);
    float4 w1 = __ldcs(w4 + lane + 32);
    float4 w2 = __ldcs(w4 + lane + 64);
    float4 w3 = __ldcs(w4 + lane + 96);
    float4 a0 = sa4[lane], a1 = sa4[lane + 32], a2 = sa4[lane + 64], a3 = sa4[lane + 96];
    float4 v0 = __ldcs(v4 + lane);
    float4 v1 = __ldcs(v4 + lane + 32);
    float4 v2 = __ldcs(v4 + lane + 64);
    float4 v3 = __ldcs(v4 + lane + 96);
    float4 b0 = sb4[lane], b1 = sb4[lane + 32], b2 = sb4[lane + 64], b3 = sb4[lane + 96];

    float4 c0 = make_float4(a0.x*w0.x + b0.x*v0.x, a0.y*w0.y + b0.y*v0.y,
                            a0.z*w0.z + b0.z*v0.z, a0.w*w0.w + b0.w*v0.w);
    float4 c1 = make_float4(a1.x*w1.x + b1.x*v1.x, a1.y*w1.y + b1.y*v1.y,
                            a1.z*w1.z + b1.z*v1.z, a1.w*w1.w + b1.w*v1.w);
    float4 c2 = make_float4(a2.x*w2.x + b2.x*v2.x, a2.y*w2.y + b2.y*v2.y,
                            a2.z*w2.z + b2.z*v2.z, a2.w*w2.w + b2.w*v2.w);
    float4 c3 = make_float4(a3.x*w3.x + b3.x*v3.x, a3.y*w3.y + b3.y*v3.y,
                            a3.z*w3.z + b3.z*v3.z, a3.w*w3.w + b3.w*v3.w);

    const float bs = bias[row];

    if (cnt <= CAP) {
        int i = 0;
        for (; i + 2 <= cnt; i += 2) {
            const int b0i = p0 >> 16, s0 = p0 & 0xffff;
            const int b1i = p1 >> 16, s1 = p1 & 0xffff;
            const uint2* x0 = reinterpret_cast<const uint2*>(g_Xh + (size_t)b0i * DQ);
            const uint2* x1 = reinterpret_cast<const uint2*>(g_Xh + (size_t)b1i * DQ);

            uint2 u00 = x0[lane], u01 = x0[lane + 32], u02 = x0[lane + 64], u03 = x0[lane + 96];
            uint2 u10 = x1[lane], u11 = x1[lane + 32], u12 = x1[lane + 64], u13 = x1[lane + 96];

            if (i + 2 < cnt) {                       // prefetch next pair words
                p0 = slots[i + 2];
                p1 = (i + 3 < cnt) ? slots[i + 3] : 0;
            }

            float r0 = dot4h(u00, c0) + dot4h(u01, c1) + dot4h(u02, c2) + dot4h(u03, c3);
            float r1 = dot4h(u10, c0) + dot4h(u11, c1) + dot4h(u12, c2) + dot4h(u13, c3);

            #pragma unroll
            for (int o = 16; o > 0; o >>= 1) {
                r0 += __shfl_xor_sync(0xffffffffu, r0, o);
                r1 += __shfl_xor_sync(0xffffffffu, r1, o);
            }
            if (lane == 0) {
                out[b0i * SQ + s0] = r0 + bs;
                out[b1i * SQ + s1] = r1 + bs;
            }
        }
        if (i < cnt) {
            const int b0i = p0 >> 16, s0 = p0 & 0xffff;
            const uint2* x0 = reinterpret_cast<const uint2*>(g_Xh + (size_t)b0i * DQ);
            uint2 u00 = x0[lane], u01 = x0[lane + 32], u02 = x0[lane + 64], u03 = x0[lane + 96];
            float r0 = dot4h(u00, c0) + dot4h(u01, c1) + dot4h(u02, c2) + dot4h(u03, c3);
            #pragma unroll
            for (int o = 16; o > 0; o >>= 1)
                r0 += __shfl_xor_sync(0xffffffffu, r0, o);
            if (lane == 0)
                out[b0i * SQ + s0] = r0 + bs;
        }
    } else {
        // Overflow safety net (statistically never taken): the stored slot
        // subset is nondeterministic, so recompute ALL refs of this row by
        // rescanning the shortlist. Each ref's output is independent.
        const bool is32 = detect_is32(shortlist, lane);
        const int*       sl32 = (const int*)shortlist;
        const long long* sl64 = (const long long*)shortlist;
        #pragma unroll 1
        for (int t = 0; t < 512 * SQ; t++) {
            const int idx = is32 ? sl32[t] : (int)sl64[t];
            if (idx != row) continue;
            const int b0i = t >> 9, s0 = t & (SQ - 1);
            const uint2* x0 = reinterpret_cast<const uint2*>(g_Xh + (size_t)b0i * DQ);
            uint2 u00 = x0[lane], u01 = x0[lane + 32], u02 = x0[lane + 64], u03 = x0[lane + 96];
            float r0 = dot4h(u00, c0) + dot4h(u01, c1) + dot4h(u02, c2) + dot4h(u03, c3);
            #pragma unroll
            for (int o = 16; o > 0; o >>= 1)
                r0 += __shfl_xor_sync(0xffffffffu, r0, o);
            if (lane == 0)
                out[b0i * SQ + s0] = r0 + bs;
        }
    }
}

extern "C" void kernel_launch(void* const* d_in, const int* in_sizes, int n_in,
                              void* d_out, int out_size) {
    const float* input     = (const float*)d_in[0];      // [B, D]
    const float* labels    = (const float*)d_in[1];      // [L, D]  (v)
    const float* weight    = (const float*)d_in[2];      // [L, D]  (u)
    const float* alpha     = (const float*)d_in[3];      // [1, D]
    const float* beta      = (const float*)d_in[4];      // [1, D]
    const float* bias      = (const float*)d_in[5];      // [L]
    const void*  shortlist = d_in[6];                    // [B, S] int32 or int64
    float*       out       = (float*)d_out;              // [B, S]

    prep_kernel<<<1152, 256>>>(shortlist, input, alpha, beta);
    score_kernel<<<LQ / 8, 256>>>(weight, labels, bias, shortlist, out);
}